// round 1
// baseline (speedup 1.0000x reference)
#include <cuda_runtime.h>
#include <cstdint>

#define N_ROWS 2048
#define K_CODES 81920
#define C_DIM 64

#define TILE_R 128
#define KSTEP 64
#define KCHUNK 4096
#define NTHREADS 256

// Scratch (device globals: no allocation allowed)
__device__ float g_enorm[K_CODES];
__device__ float g_znorm[N_ROWS];
__device__ unsigned long long g_best[N_ROWS];
__device__ double g_rowloss[N_ROWS];

// ---------------------------------------------------------------------------
// Prep: enorm[k] = sum_c emb[k][c]^2 ; znorm[n] = sum_c z[n][c]^2 ; init best
// (order-dependent rounding of these sums cannot flip the argmin: znorm
//  differences are integer multiples of the d2 rounding grid; enorm error
//  is ~1e-16 abs)
// ---------------------------------------------------------------------------
__global__ void vq_prep_kernel(const float* __restrict__ z,
                               const float* __restrict__ emb) {
    int t = blockIdx.x * blockDim.x + threadIdx.x;
    if (t < K_CODES) {
        const float* e = emb + (size_t)t * C_DIM;
        float s = 0.f;
#pragma unroll
        for (int c = 0; c < C_DIM; ++c) s = fmaf(e[c], e[c], s);
        g_enorm[t] = s;
    } else {
        int r = t - K_CODES;
        if (r < N_ROWS) {
            const float* zr = z + (size_t)r * C_DIM;
            float s = 0.f;
#pragma unroll
            for (int c = 0; c < C_DIM; ++c) s = fmaf(zr[c], zr[c], s);
            g_znorm[r] = s;
            g_best[r] = 0xFFFFFFFFFFFFFFFFull;
        }
    }
}

// ---------------------------------------------------------------------------
// Main: for each (row, code) compute fp32 dot, emulate the reference's exact
// fp32 rounding of d2 = (znorm - 2*dot) + enorm, keep running packed min
// (d2_bits<<32 | idx) so ties resolve to the FIRST index like jnp.argmin.
// ---------------------------------------------------------------------------
__global__ __launch_bounds__(NTHREADS, 2)
void vq_main_kernel(const float* __restrict__ z, const float* __restrict__ emb) {
    // static smem: sZt 64x128 transposed (32768 B) + sE 64x64 (16384 B) = 48 KB
    __shared__ float sZt[C_DIM * TILE_R];
    __shared__ float sE[KSTEP * C_DIM];

    const int tid = threadIdx.x;
    const int tx = tid & 15;
    const int ty = tid >> 4;
    const int rowBase = blockIdx.y * TILE_R;
    const int kBase = blockIdx.x * KCHUNK;

    // Load z tile transposed: sZt[c*128 + r] = z[rowBase+r][c]
    for (int i = tid; i < TILE_R * C_DIM; i += NTHREADS) {
        int r = i >> 6, c = i & 63;
        sZt[c * TILE_R + r] = z[(size_t)(rowBase + r) * C_DIM + c];
    }

    float zn[8];
#pragma unroll
    for (int i = 0; i < 8; ++i) zn[i] = g_znorm[rowBase + ty * 8 + i];

    unsigned long long best[8];
#pragma unroll
    for (int i = 0; i < 8; ++i) best[i] = 0xFFFFFFFFFFFFFFFFull;

    const int kl = tid >> 2;          // 0..63  (code within step)
    const int c0 = (tid & 3) * 4;     // 0,4,8,12

    for (int k0 = kBase; k0 < kBase + KCHUNK; k0 += KSTEP) {
        __syncthreads();
        // Load 64-code tile transposed: sE[c*64 + kl] = emb[k0+kl][c]
#pragma unroll
        for (int j = 0; j < 4; ++j) {
            int c = c0 + 16 * j;
            float4 v = *reinterpret_cast<const float4*>(
                emb + (size_t)(k0 + kl) * C_DIM + c);
            sE[(c + 0) * KSTEP + kl] = v.x;
            sE[(c + 1) * KSTEP + kl] = v.y;
            sE[(c + 2) * KSTEP + kl] = v.z;
            sE[(c + 3) * KSTEP + kl] = v.w;
        }
        __syncthreads();

        float acc[8][4];
#pragma unroll
        for (int i = 0; i < 8; ++i)
#pragma unroll
            for (int j = 0; j < 4; ++j) acc[i][j] = 0.f;

#pragma unroll 4
        for (int c = 0; c < C_DIM; ++c) {
            float e0 = sE[c * KSTEP + tx];
            float e1 = sE[c * KSTEP + tx + 16];
            float e2 = sE[c * KSTEP + tx + 32];
            float e3 = sE[c * KSTEP + tx + 48];
#pragma unroll
            for (int i = 0; i < 8; ++i) {
                float zv = sZt[c * TILE_R + ty * 8 + i];
                acc[i][0] = fmaf(zv, e0, acc[i][0]);
                acc[i][1] = fmaf(zv, e1, acc[i][1]);
                acc[i][2] = fmaf(zv, e2, acc[i][2]);
                acc[i][3] = fmaf(zv, e3, acc[i][3]);
            }
        }

        float en[4];
#pragma unroll
        for (int j = 0; j < 4; ++j) en[j] = g_enorm[k0 + tx + 16 * j];

#pragma unroll
        for (int i = 0; i < 8; ++i) {
#pragma unroll
            for (int j = 0; j < 4; ++j) {
                // exact reference rounding: ((znorm - 2*dot) + enorm), fp32 each step
                float d2 = __fadd_rn(__fsub_rn(zn[i], __fmul_rn(2.0f, acc[i][j])),
                                     en[j]);
                unsigned int b = __float_as_uint(d2);
                b = (b & 0x80000000u) ? ~b : (b | 0x80000000u);  // orderable
                unsigned long long p =
                    ((unsigned long long)b << 32) | (unsigned)(k0 + tx + 16 * j);
                best[i] = min(best[i], p);
            }
        }
    }

    // CTA-level merge (alias smem; sZt/sE dead now)
    __syncthreads();
    unsigned long long* sB = reinterpret_cast<unsigned long long*>(sZt);
#pragma unroll
    for (int i = 0; i < 8; ++i) sB[(ty * 8 + i) * 16 + tx] = best[i];
    __syncthreads();
    if (tid < TILE_R) {
        unsigned long long m = sB[tid * 16];
#pragma unroll
        for (int t = 1; t < 16; ++t) m = min(m, sB[tid * 16 + t]);
        atomicMin(&g_best[rowBase + tid], m);
    }
}

// ---------------------------------------------------------------------------
// Finalize: gather codebook rows, write quantized_st = fl(z + fl(q - z)),
// per-row loss partials (double, deterministic tree), idx as float.
// ---------------------------------------------------------------------------
__global__ void vq_finalize_kernel(const float* __restrict__ z,
                                   const float* __restrict__ emb,
                                   float* __restrict__ out, int out_size) {
    __shared__ double sD[256];
    int tid = threadIdx.x;
    int rl = tid >> 6;      // 0..3
    int lane = tid & 63;    // channel
    int row = blockIdx.x * 4 + rl;

    unsigned long long b = g_best[row];
    unsigned int idx = (unsigned int)(b & 0xFFFFFFFFull);

    float q = emb[(size_t)idx * C_DIM + lane];
    float zv = z[(size_t)row * C_DIM + lane];
    float qs = __fadd_rn(zv, __fsub_rn(q, zv));   // z + (quantized - z)
    if ((size_t)row * C_DIM + lane < (size_t)out_size)
        out[(size_t)row * C_DIM + lane] = qs;

    float s = __fsub_rn(zv, q);
    sD[tid] = (double)__fmul_rn(s, s);
    __syncthreads();
#pragma unroll
    for (int st = 32; st >= 1; st >>= 1) {
        if (lane < st) sD[tid] += sD[tid + st];
        __syncthreads();
    }
    if (lane == 0) {
        g_rowloss[row] = sD[tid];
        if (out_size >= 133122) out[131074 + row] = (float)idx;
    }
}

__global__ void vq_loss_kernel(float* __restrict__ out, int out_size) {
    __shared__ double sD[256];
    int tid = threadIdx.x;
    double s = 0.0;
    for (int r = tid; r < N_ROWS; r += 256) s += g_rowloss[r];  // deterministic
    sD[tid] = s;
    __syncthreads();
#pragma unroll
    for (int st = 128; st >= 1; st >>= 1) {
        if (tid < st) sD[tid] += sD[tid + st];
        __syncthreads();
    }
    if (tid == 0 && out_size >= 133122) {
        float m = (float)(sD[0] / 131072.0);
        out[131072] = m;  // vq_loss
        out[131073] = m;  // commitment_loss (identical value in fp arithmetic)
    }
}

// ---------------------------------------------------------------------------
extern "C" void kernel_launch(void* const* d_in, const int* in_sizes, int n_in,
                              void* d_out, int out_size) {
    const float* z = (const float*)d_in[0];
    const float* emb = (const float*)d_in[1];
    // defensive: detect swapped input order by element counts
    if (n_in >= 2 && in_sizes[0] == K_CODES * C_DIM && in_sizes[1] == N_ROWS * C_DIM) {
        const float* t = z; z = emb; emb = t;
    }
    float* out = (float*)d_out;

    // (K_CODES + N_ROWS) / 256 = 328 exactly
    vq_prep_kernel<<<328, NTHREADS>>>(z, emb);
    vq_main_kernel<<<dim3(K_CODES / KCHUNK, N_ROWS / TILE_R), NTHREADS>>>(z, emb);
    vq_finalize_kernel<<<N_ROWS / 4, 256>>>(z, emb, out, out_size);
    vq_loss_kernel<<<1, 256>>>(out, out_size);
}

// round 2
// speedup vs baseline: 1.3457x; 1.3457x over previous
#include <cuda_runtime.h>
#include <cstdint>

#define N_ROWS 2048
#define K_CODES 81920
#define C_DIM 64
#define TILE_R 128
#define TILE_K 128
#define NTHREADS 256

typedef unsigned long long u64;

// Scratch (device globals: no allocation allowed)
__device__ float g_enorm[K_CODES];
__device__ float g_znorm[N_ROWS];
__device__ u64 g_best[N_ROWS];
__device__ double g_rowloss[N_ROWS];

// ---------------------------------------------------------------------------
// Packed f32x2 helpers (Blackwell FFMA2/FADD2/FMUL2 — RN per lane, bitwise
// identical to two scalar fp32 ops)
// ---------------------------------------------------------------------------
__device__ __forceinline__ u64 ffma2(u64 a, u64 b, u64 c) {
    u64 d; asm("fma.rn.f32x2 %0, %1, %2, %3;" : "=l"(d) : "l"(a), "l"(b), "l"(c));
    return d;
}
__device__ __forceinline__ u64 fmul2(u64 a, u64 b) {
    u64 d; asm("mul.rn.f32x2 %0, %1, %2;" : "=l"(d) : "l"(a), "l"(b));
    return d;
}
__device__ __forceinline__ u64 fadd2(u64 a, u64 b) {
    u64 d; asm("add.rn.f32x2 %0, %1, %2;" : "=l"(d) : "l"(a), "l"(b));
    return d;
}
__device__ __forceinline__ u64 pack2(float lo, float hi) {
    u64 d; asm("mov.b64 %0, {%1, %2};" : "=l"(d) : "f"(lo), "f"(hi));
    return d;
}
__device__ __forceinline__ void unpack2(u64 v, float& lo, float& hi) {
    asm("mov.b64 {%0, %1}, %2;" : "=f"(lo), "=f"(hi) : "l"(v));
}

// ---------------------------------------------------------------------------
// Prep: enorm[k], znorm[n], init g_best
// ---------------------------------------------------------------------------
__global__ void vq_prep_kernel(const float* __restrict__ z,
                               const float* __restrict__ emb) {
    int t = blockIdx.x * blockDim.x + threadIdx.x;
    if (t < K_CODES) {
        const float* e = emb + (size_t)t * C_DIM;
        float s = 0.f;
#pragma unroll
        for (int c = 0; c < C_DIM; ++c) s = fmaf(e[c], e[c], s);
        g_enorm[t] = s;
    } else {
        int r = t - K_CODES;
        if (r < N_ROWS) {
            const float* zr = z + (size_t)r * C_DIM;
            float s = 0.f;
#pragma unroll
            for (int c = 0; c < C_DIM; ++c) s = fmaf(zr[c], zr[c], s);
            g_znorm[r] = s;
            g_best[r] = 0xFFFFFFFFFFFFFFFFull;
        }
    }
}

// ---------------------------------------------------------------------------
// Main: 128 rows x 128 codes per CTA, f32x2-packed along row pairs.
// d2 = fl(fl(znorm + fl(-2*dot)) + enorm) — bitwise identical to the
// reference's fl(fl(znorm - fl(2*dot)) + enorm). First-index ties:
// within-thread strict < over increasing k; across threads/CTAs packed
// (orderable_bits<<32 | idx) min.
// ---------------------------------------------------------------------------
__global__ __launch_bounds__(NTHREADS, 2)
void vq_main_kernel(const float* __restrict__ z, const float* __restrict__ emb) {
    extern __shared__ float smem[];       // 16384 floats = 64 KB
    float* sZt = smem;                    // [c][r]  c-stride 128
    float* sE  = smem + C_DIM * TILE_R;   // [c][k]  c-stride 128

    const int tid = threadIdx.x;
    const int tx = tid & 15;              // code lane
    const int ty = tid >> 4;              // row group (8 rows each)
    const int rowBase = blockIdx.y * TILE_R;
    const int kBase   = blockIdx.x * TILE_K;

    // Load tiles transposed. Mapping r = i&127, c4 = i>>7 makes STS.32
    // conflict-free (consecutive lanes -> consecutive r/k).
#pragma unroll
    for (int it = 0; it < 8; ++it) {
        int i = tid + NTHREADS * it;
        int r = i & 127, c4 = i >> 7;
        float4 v = *reinterpret_cast<const float4*>(
            z + (size_t)(rowBase + r) * C_DIM + c4 * 4);
        sZt[(c4 * 4 + 0) * TILE_R + r] = v.x;
        sZt[(c4 * 4 + 1) * TILE_R + r] = v.y;
        sZt[(c4 * 4 + 2) * TILE_R + r] = v.z;
        sZt[(c4 * 4 + 3) * TILE_R + r] = v.w;
        float4 w = *reinterpret_cast<const float4*>(
            emb + (size_t)(kBase + r) * C_DIM + c4 * 4);
        sE[(c4 * 4 + 0) * TILE_K + r] = w.x;
        sE[(c4 * 4 + 1) * TILE_K + r] = w.y;
        sE[(c4 * 4 + 2) * TILE_K + r] = w.z;
        sE[(c4 * 4 + 3) * TILE_K + r] = w.w;
    }

    float zn[8];
#pragma unroll
    for (int l = 0; l < 8; ++l) zn[l] = g_znorm[rowBase + ty * 8 + l];

    __syncthreads();

    // acc[rp][j]: rows (ty*8+2rp, ty*8+2rp+1), code kBase + tx + 16*j
    u64 acc[4][8];
#pragma unroll
    for (int rp = 0; rp < 4; ++rp)
#pragma unroll
        for (int j = 0; j < 8; ++j) acc[rp][j] = 0ull;  // (0.f, 0.f)

#pragma unroll 4
    for (int c = 0; c < C_DIM; ++c) {
        const u64* zrow = reinterpret_cast<const u64*>(sZt + c * TILE_R);
        u64 zp[4];
#pragma unroll
        for (int rp = 0; rp < 4; ++rp) zp[rp] = zrow[ty * 4 + rp];  // LDS.64
        const float* erow = sE + c * TILE_K;
#pragma unroll
        for (int j = 0; j < 8; ++j) {
            float e = erow[tx + 16 * j];     // conflict-free LDS.32
            u64 ee = pack2(e, e);
#pragma unroll
            for (int rp = 0; rp < 4; ++rp)
                acc[rp][j] = ffma2(zp[rp], ee, acc[rp][j]);
        }
    }

    // Epilogue: exact-rounded d2 + per-row running min (first-index ties)
    const u64 NEG2 = 0xC0000000C0000000ull;  // (-2.f, -2.f)
    float best[8];
    int bidx[8];
#pragma unroll
    for (int l = 0; l < 8; ++l) {
        best[l] = __int_as_float(0x7F800000);  // +inf
        bidx[l] = kBase + tx;
    }
    u64 znp[4];
#pragma unroll
    for (int rp = 0; rp < 4; ++rp) znp[rp] = pack2(zn[2 * rp], zn[2 * rp + 1]);

#pragma unroll
    for (int j = 0; j < 8; ++j) {
        int k = kBase + tx + 16 * j;
        float en = g_enorm[k];
        u64 en2 = pack2(en, en);
#pragma unroll
        for (int rp = 0; rp < 4; ++rp) {
            u64 m  = fmul2(acc[rp][j], NEG2);     // fl(-2*dot) = -fl(2*dot)
            u64 t  = fadd2(znp[rp], m);           // fl(znorm - 2*dot)
            u64 d2 = fadd2(t, en2);               // fl(... + enorm)
            float lo, hi;
            unpack2(d2, lo, hi);
            int r0 = 2 * rp, r1 = 2 * rp + 1;
            if (lo < best[r0]) { best[r0] = lo; bidx[r0] = k; }
            if (hi < best[r1]) { best[r1] = hi; bidx[r1] = k; }
        }
    }

    // CTA merge: padded (stride-17) smem, then one atomicMin per row
    __syncthreads();
    u64* sB = reinterpret_cast<u64*>(smem);
#pragma unroll
    for (int l = 0; l < 8; ++l) {
        unsigned int b = __float_as_uint(best[l]);
        b = (b & 0x80000000u) ? ~b : (b | 0x80000000u);  // orderable
        sB[(ty * 8 + l) * 17 + tx] = ((u64)b << 32) | (unsigned)bidx[l];
    }
    __syncthreads();
    if (tid < TILE_R) {
        u64 m = sB[tid * 17];
#pragma unroll
        for (int t = 1; t < 16; ++t) m = min(m, sB[tid * 17 + t]);
        atomicMin(&g_best[rowBase + tid], m);
    }
}

// ---------------------------------------------------------------------------
// Finalize: gather, quantized_st = fl(z + fl(q - z)), per-row loss partials
// ---------------------------------------------------------------------------
__global__ void vq_finalize_kernel(const float* __restrict__ z,
                                   const float* __restrict__ emb,
                                   float* __restrict__ out, int out_size) {
    __shared__ double sD[256];
    int tid = threadIdx.x;
    int rl = tid >> 6;
    int lane = tid & 63;
    int row = blockIdx.x * 4 + rl;

    u64 b = g_best[row];
    unsigned int idx = (unsigned int)(b & 0xFFFFFFFFull);

    float q = emb[(size_t)idx * C_DIM + lane];
    float zv = z[(size_t)row * C_DIM + lane];
    float qs = __fadd_rn(zv, __fsub_rn(q, zv));
    if ((size_t)row * C_DIM + lane < (size_t)out_size)
        out[(size_t)row * C_DIM + lane] = qs;

    float s = __fsub_rn(zv, q);
    sD[tid] = (double)__fmul_rn(s, s);
    __syncthreads();
#pragma unroll
    for (int st = 32; st >= 1; st >>= 1) {
        if (lane < st) sD[tid] += sD[tid + st];
        __syncthreads();
    }
    if (lane == 0) {
        g_rowloss[row] = sD[tid];
        if (out_size >= 133122) out[131074 + row] = (float)idx;
    }
}

__global__ void vq_loss_kernel(float* __restrict__ out, int out_size) {
    __shared__ double sD[256];
    int tid = threadIdx.x;
    double s = 0.0;
    for (int r = tid; r < N_ROWS; r += 256) s += g_rowloss[r];
    sD[tid] = s;
    __syncthreads();
#pragma unroll
    for (int st = 128; st >= 1; st >>= 1) {
        if (tid < st) sD[tid] += sD[tid + st];
        __syncthreads();
    }
    if (tid == 0 && out_size >= 133122) {
        float m = (float)(sD[0] / 131072.0);
        out[131072] = m;
        out[131073] = m;
    }
}

// ---------------------------------------------------------------------------
extern "C" void kernel_launch(void* const* d_in, const int* in_sizes, int n_in,
                              void* d_out, int out_size) {
    const float* z = (const float*)d_in[0];
    const float* emb = (const float*)d_in[1];
    if (n_in >= 2 && in_sizes[0] == K_CODES * C_DIM && in_sizes[1] == N_ROWS * C_DIM) {
        const float* t = z; z = emb; emb = t;
    }
    float* out = (float*)d_out;

    // 64 KB dynamic smem needs opt-in (idempotent; host-side, capture-safe)
    cudaFuncSetAttribute(vq_main_kernel,
                         cudaFuncAttributeMaxDynamicSharedMemorySize, 65536);

    vq_prep_kernel<<<328, NTHREADS>>>(z, emb);
    vq_main_kernel<<<dim3(K_CODES / TILE_K, N_ROWS / TILE_R), NTHREADS,
                     65536>>>(z, emb);
    vq_finalize_kernel<<<N_ROWS / 4, 256>>>(z, emb, out, out_size);
    vq_loss_kernel<<<1, 256>>>(out, out_size);
}

// round 4
// speedup vs baseline: 2.4114x; 1.7920x over previous
#include <cuda_runtime.h>
#include <cuda_bf16.h>

typedef unsigned int u32;
typedef unsigned long long u64;

#define N_ROWS 2048
#define K_CODES 81920
#define C_DIM 64
#define M_TILE 128
#define N_TILE 128
#define CHUNK 2048
#define TILES (CHUNK / N_TILE)     // 16
#define NCHUNKS (K_CODES / CHUNK)  // 40
#define PITCH 72                   // bf16 elems per smem row (conflict-free)
#define CAP 2048

// ---------------- device scratch (no allocation allowed) -------------------
__device__ __nv_bfloat16 g_zbf[N_ROWS * C_DIM];
__device__ __nv_bfloat16 g_ebf[K_CODES * C_DIM];
__device__ float g_enorm[K_CODES];
__device__ float g_znorm[N_ROWS];
__device__ float g_sumabs[N_ROWS];
__device__ u32 g_smin[N_ROWS];     // orderable-uint float
__device__ u32 g_emax;             // bits of max|emb| (>=0)
__device__ int g_cnt[N_ROWS];
__device__ int g_cand[N_ROWS * CAP];
__device__ double g_rowloss[N_ROWS];

// ---------------- helpers ---------------------------------------------------
__device__ __forceinline__ u32 f2o(float f) {
    u32 b = __float_as_uint(f);
    return (b & 0x80000000u) ? ~b : (b | 0x80000000u);
}
__device__ __forceinline__ float o2f(u32 o) {
    u32 b = (o & 0x80000000u) ? (o ^ 0x80000000u) : ~o;
    return __uint_as_float(b);
}
__device__ __forceinline__ u32 smem_u32(const void* p) {
    u32 a; asm("{ .reg .u64 t; cvta.to.shared.u64 t, %1; cvt.u32.u64 %0, t; }"
               : "=r"(a) : "l"(p));
    return a;
}
__device__ __forceinline__ void cpa16(u32 dst, const void* src) {
    asm volatile("cp.async.cg.shared.global [%0], [%1], 16;" :: "r"(dst), "l"(src));
}
__device__ __forceinline__ void cpa_commit() {
    asm volatile("cp.async.commit_group;");
}
template <int N> __device__ __forceinline__ void cpa_wait() {
    asm volatile("cp.async.wait_group %0;" :: "n"(N));
}
// m16n8k16 row.col bf16 -> f32, accumulate in place
__device__ __forceinline__ void mma16816(float* d, const u32* a, u32 b0, u32 b1) {
    asm volatile(
        "mma.sync.aligned.m16n8k16.row.col.f32.bf16.bf16.f32 "
        "{%0,%1,%2,%3},{%4,%5,%6,%7},{%8,%9},{%0,%1,%2,%3};"
        : "+f"(d[0]), "+f"(d[1]), "+f"(d[2]), "+f"(d[3])
        : "r"(a[0]), "r"(a[1]), "r"(a[2]), "r"(a[3]), "r"(b0), "r"(b1));
}

// ---------------------------------------------------------------------------
// Prep: norms (bit-identical sequential fmaf, as in R1/R2), bf16 copies,
// sum|z| per row, max|e| global, reset smin/cnt.
// ---------------------------------------------------------------------------
__global__ void vq_prep(const float* __restrict__ z, const float* __restrict__ emb) {
    __shared__ float sMax[256];
    int tid = threadIdx.x;
    int t = blockIdx.x * 256 + tid;
    float lmax = 0.f;
    if (t < K_CODES) {
        const float* e = emb + (size_t)t * C_DIM;
        float s = 0.f;
#pragma unroll
        for (int c = 0; c < C_DIM; ++c) {
            float v = e[c];
            s = fmaf(v, v, s);
            lmax = fmaxf(lmax, fabsf(v));
            g_ebf[(size_t)t * C_DIM + c] = __float2bfloat16_rn(v);
        }
        g_enorm[t] = s;
    } else if (t < K_CODES + N_ROWS) {
        int r = t - K_CODES;
        const float* zr = z + (size_t)r * C_DIM;
        float s = 0.f, sa = 0.f;
#pragma unroll
        for (int c = 0; c < C_DIM; ++c) {
            float v = zr[c];
            s = fmaf(v, v, s);
            sa += fabsf(v);
            g_zbf[(size_t)r * C_DIM + c] = __float2bfloat16_rn(v);
        }
        g_znorm[r] = s;
        g_sumabs[r] = sa;
        g_smin[r] = 0xFFFFFFFFu;
        g_cnt[r] = 0;
    }
    sMax[tid] = lmax;
    __syncthreads();
#pragma unroll
    for (int st = 128; st >= 1; st >>= 1) {
        if (tid < st) sMax[tid] = fmaxf(sMax[tid], sMax[tid + st]);
        __syncthreads();
    }
    if (tid == 0 && sMax[0] > 0.f) atomicMax(&g_emax, __float_as_uint(sMax[0]));
}

// ---------------------------------------------------------------------------
// bf16 HMMA filter GEMM. pass=0: per-row min of s=enorm-2dot. pass=1: collect
// candidates with s <= smin + rigorous margin. Both passes compute s via the
// identical instruction sequence -> bitwise identical.
// ---------------------------------------------------------------------------
__global__ __launch_bounds__(256, 2) void vq_mma_pass(int pass) {
    extern __shared__ char smem[];
    __nv_bfloat16* sA = (__nv_bfloat16*)smem;               // 128 x PITCH
    const u32 sbase = smem_u32(smem);
    // offsets: A 0..18432, B0 18432, B1 36864, En0 55296, En1 55808, sMin 56320
    float* sMin = (float*)(smem + 56320);

    const int tid = threadIdx.x, lane = tid & 31, wid = tid >> 5;
    const int warp_m = wid >> 1, warp_n = wid & 1;
    const int g = lane >> 2, tq = lane & 3;
    const int rowBase = blockIdx.y * M_TILE;
    const int kChunk = blockIdx.x * CHUNK;

    // group 0: A tile + B tile 0 + En0
#pragma unroll
    for (int j = 0; j < 4; ++j) {
        int idx = tid + 256 * j, r = idx >> 3, sg = idx & 7;
        cpa16(sbase + r * (PITCH * 2) + sg * 16,
              g_zbf + (size_t)(rowBase + r) * C_DIM + sg * 8);
        cpa16(sbase + 18432 + r * (PITCH * 2) + sg * 16,
              g_ebf + (size_t)(kChunk + r) * C_DIM + sg * 8);
    }
    if (tid < 32) cpa16(sbase + 55296 + tid * 16, g_enorm + kChunk + tid * 4);
    cpa_commit();

    float thr[2][2], runmin[2][2];
#pragma unroll
    for (int am = 0; am < 2; ++am)
#pragma unroll
        for (int h = 0; h < 2; ++h) {
            runmin[am][h] = __int_as_float(0x7F800000);
            if (pass) {
                int r = rowBase + warp_m * 32 + am * 16 + g + 8 * h;
                float smin = o2f(g_smin[r]);
                float emax = __uint_as_float(g_emax);
                // 4*errdot + tie-bin + slack (all worst-case over-bounds)
                float margin = 4.0f * 0.0082f * emax * g_sumabs[r]
                             + g_znorm[r] * 9.5367431640625e-07f + 2e-6f;
                thr[am][h] = smin + margin;
            } else thr[am][h] = 0.f;
        }

    for (int t = 0; t < TILES; ++t) {
        int buf = t & 1;
        if (t + 1 < TILES) {
            u32 db = sbase + (((t + 1) & 1) ? 36864u : 18432u);
            const __nv_bfloat16* src = g_ebf + (size_t)(kChunk + (t + 1) * N_TILE) * C_DIM;
#pragma unroll
            for (int j = 0; j < 4; ++j) {
                int idx = tid + 256 * j, r = idx >> 3, sg = idx & 7;
                cpa16(db + r * (PITCH * 2) + sg * 16, src + (size_t)r * C_DIM + sg * 8);
            }
            if (tid < 32)
                cpa16(sbase + (((t + 1) & 1) ? 55808u : 55296u) + tid * 16,
                      g_enorm + kChunk + (t + 1) * N_TILE + tid * 4);
            cpa_commit();
            cpa_wait<1>();
        } else {
            cpa_wait<0>();
        }
        __syncthreads();

        const __nv_bfloat16* B = (__nv_bfloat16*)(smem + (buf ? 36864 : 18432));
        const float* En = (const float*)(smem + (buf ? 55808 : 55296));

        float d[2][8][4];
#pragma unroll
        for (int am = 0; am < 2; ++am)
#pragma unroll
            for (int bn = 0; bn < 8; ++bn)
#pragma unroll
                for (int e = 0; e < 4; ++e) d[am][bn][e] = 0.f;

#pragma unroll
        for (int ks = 0; ks < 4; ++ks) {
            u32 a[2][4];
#pragma unroll
            for (int am = 0; am < 2; ++am) {
                int r0 = warp_m * 32 + am * 16 + g;
                a[am][0] = *(const u32*)(sA + r0 * PITCH + ks * 16 + tq * 2);
                a[am][1] = *(const u32*)(sA + (r0 + 8) * PITCH + ks * 16 + tq * 2);
                a[am][2] = *(const u32*)(sA + r0 * PITCH + ks * 16 + 8 + tq * 2);
                a[am][3] = *(const u32*)(sA + (r0 + 8) * PITCH + ks * 16 + 8 + tq * 2);
            }
#pragma unroll
            for (int bn = 0; bn < 8; ++bn) {
                int n = warp_n * 64 + bn * 8 + g;
                u32 b0 = *(const u32*)(B + n * PITCH + ks * 16 + tq * 2);
                u32 b1 = *(const u32*)(B + n * PITCH + ks * 16 + 8 + tq * 2);
                mma16816(d[0][bn], a[0], b0, b1);
                mma16816(d[1][bn], a[1], b0, b1);
            }
        }

        // epilogue: s = enorm - 2*dot (fp32, identical both passes)
#pragma unroll
        for (int am = 0; am < 2; ++am)
#pragma unroll
            for (int bn = 0; bn < 8; ++bn)
#pragma unroll
                for (int e = 0; e < 4; ++e) {
                    int col = warp_n * 64 + bn * 8 + 2 * tq + (e & 1);
                    int h = e >> 1;
                    float s = __fsub_rn(En[col], __fmul_rn(2.0f, d[am][bn][e]));
                    if (!pass) {
                        runmin[am][h] = fminf(runmin[am][h], s);
                    } else if (s <= thr[am][h]) {
                        int row = rowBase + warp_m * 32 + am * 16 + g + 8 * h;
                        int k = kChunk + t * N_TILE + col;
                        int ix = atomicAdd(&g_cnt[row], 1);
                        if (ix < CAP) g_cand[(size_t)row * CAP + ix] = k;
                    }
                }
        __syncthreads();
    }

    if (!pass) {
#pragma unroll
        for (int am = 0; am < 2; ++am)
#pragma unroll
            for (int h = 0; h < 2; ++h) {
                float v = runmin[am][h];
                v = fminf(v, __shfl_xor_sync(0xFFFFFFFFu, v, 1));
                v = fminf(v, __shfl_xor_sync(0xFFFFFFFFu, v, 2));
                if (tq == 0) {
                    int r = warp_m * 32 + am * 16 + g + 8 * h;
                    sMin[r * 2 + warp_n] = v;
                }
            }
        __syncthreads();
        if (tid < M_TILE) {
            float v = fminf(sMin[tid * 2], sMin[tid * 2 + 1]);
            atomicMin(&g_smin[rowBase + tid], f2o(v));
        }
    }
}

// ---------------------------------------------------------------------------
// Rescore candidates exactly (R1-proven fp32 path) + finalize outputs.
// One warp per row. Packed (orderable<<32 | idx) min = first-index ties.
// ---------------------------------------------------------------------------
__global__ void vq_rescore_finalize(const float* __restrict__ z,
                                    const float* __restrict__ emb,
                                    float* __restrict__ out, int out_size) {
    __shared__ float sZ[8][C_DIM];
    int tid = threadIdx.x, lane = tid & 31, w = tid >> 5;
    int rowBlk = blockIdx.x * 8;
    for (int i = tid; i < 8 * C_DIM; i += 256) {
        int r = i >> 6, c = i & 63;
        sZ[r][c] = z[(size_t)(rowBlk + r) * C_DIM + c];
    }
    __syncthreads();

    int row = rowBlk + w;
    float znorm = g_znorm[row];
    int cnt = g_cnt[row];
    const float* zr = sZ[w];
    u64 best = 0xFFFFFFFFFFFFFFFFull;

    if (cnt <= CAP) {
        for (int i = lane; i < cnt; i += 32) {
            int k = g_cand[(size_t)row * CAP + i];
            const float* e = emb + (size_t)k * C_DIM;
            float dot = 0.f;
#pragma unroll
            for (int c = 0; c < C_DIM; ++c) dot = fmaf(zr[c], e[c], dot);
            float d2 = __fadd_rn(__fsub_rn(znorm, __fmul_rn(2.0f, dot)), g_enorm[k]);
            u64 p = ((u64)f2o(d2) << 32) | (u32)k;
            best = p < best ? p : best;
        }
    } else {  // overflow fallback: exact full scan for this row
        for (int k = lane; k < K_CODES; k += 32) {
            const float* e = emb + (size_t)k * C_DIM;
            float dot = 0.f;
#pragma unroll
            for (int c = 0; c < C_DIM; ++c) dot = fmaf(zr[c], e[c], dot);
            float d2 = __fadd_rn(__fsub_rn(znorm, __fmul_rn(2.0f, dot)), g_enorm[k]);
            u64 p = ((u64)f2o(d2) << 32) | (u32)k;
            best = p < best ? p : best;
        }
    }
#pragma unroll
    for (int st = 16; st >= 1; st >>= 1) {
        u64 o = __shfl_xor_sync(0xFFFFFFFFu, best, st);
        best = o < best ? o : best;
    }
    u32 idx = (u32)best;

    double part = 0.0;
#pragma unroll
    for (int q = 0; q < 2; ++q) {
        int c = lane + 32 * q;
        float e = emb[(size_t)idx * C_DIM + c];
        float zv = zr[c];
        if ((size_t)row * C_DIM + c < (size_t)out_size)
            out[(size_t)row * C_DIM + c] = __fadd_rn(zv, __fsub_rn(e, zv));
        float s = __fsub_rn(zv, e);
        part += (double)__fmul_rn(s, s);
    }
#pragma unroll
    for (int st = 16; st >= 1; st >>= 1)
        part += __shfl_xor_sync(0xFFFFFFFFu, part, st);
    if (lane == 0) {
        g_rowloss[row] = part;
        if (out_size >= 133122) out[131074 + row] = (float)idx;
    }
}

__global__ void vq_loss(float* __restrict__ out, int out_size) {
    __shared__ double sD[256];
    int tid = threadIdx.x;
    double s = 0.0;
    for (int r = tid; r < N_ROWS; r += 256) s += g_rowloss[r];
    sD[tid] = s;
    __syncthreads();
#pragma unroll
    for (int st = 128; st >= 1; st >>= 1) {
        if (tid < st) sD[tid] += sD[tid + st];
        __syncthreads();
    }
    if (tid == 0 && out_size >= 133122) {
        float m = (float)(sD[0] / 131072.0);
        out[131072] = m;
        out[131073] = m;
    }
}

// ---------------------------------------------------------------------------
extern "C" void kernel_launch(void* const* d_in, const int* in_sizes, int n_in,
                              void* d_out, int out_size) {
    const float* z = (const float*)d_in[0];
    const float* emb = (const float*)d_in[1];
    if (n_in >= 2 && in_sizes[0] == K_CODES * C_DIM && in_sizes[1] == N_ROWS * C_DIM) {
        const float* t = z; z = emb; emb = t;
    }
    float* out = (float*)d_out;

    cudaFuncSetAttribute(vq_mma_pass,
                         cudaFuncAttributeMaxDynamicSharedMemorySize, 57344);

    vq_prep<<<(K_CODES + N_ROWS) / 256, 256>>>(z, emb);
    vq_mma_pass<<<dim3(NCHUNKS, N_ROWS / M_TILE), 256, 57344>>>(0);
    vq_mma_pass<<<dim3(NCHUNKS, N_ROWS / M_TILE), 256, 57344>>>(1);
    vq_rescore_finalize<<<N_ROWS / 8, 256>>>(z, emb, out, out_size);
    vq_loss<<<1, 256>>>(out, out_size);
}